// round 10
// baseline (speedup 1.0000x reference)
#include <cuda_runtime.h>

#define NB 16
#define NC 64
#define NH 128
#define NW 128
#define NPIX (NH*NW)
#define TW 32

typedef unsigned long long ull;

__device__ float g_T[(size_t)NB * NC * NH * NW];

// ---- packed fp32x2 helpers (exact IEEE fp32 per lane) ----
__device__ __forceinline__ ull fma2(ull a, ull b, ull c) {
    ull d;
    asm("fma.rn.f32x2 %0, %1, %2, %3;" : "=l"(d) : "l"(a), "l"(b), "l"(c));
    return d;
}
__device__ __forceinline__ ull add2(ull a, ull b) {
    ull d; asm("add.rn.f32x2 %0, %1, %2;" : "=l"(d) : "l"(a), "l"(b)); return d;
}
__device__ __forceinline__ ull mul2(ull a, ull b) {
    ull d; asm("mul.rn.f32x2 %0, %1, %2;" : "=l"(d) : "l"(a), "l"(b)); return d;
}
__device__ __forceinline__ ull pack2(float lo, float hi) {
    ull d; asm("mov.b64 %0, {%1, %2};" : "=l"(d) : "f"(lo), "f"(hi)); return d;
}
__device__ __forceinline__ float2 unpack2(ull v) {
    float2 f; asm("mov.b64 {%0, %1}, %2;" : "=f"(f.x), "=f"(f.y) : "l"(v)); return f;
}

// smem layout (floats):
//   SY at 0     : [132][52] y (rows 0,1,130,131 zero; image row = i-2)
//   SX at 6864  : [130][56] x tile (phases 1-2 only)
//   SH21/SH11/SH7 at 6864 + f*2960 : [148][20] (16 used cols + 4 pad),
//       rows 0..9 & 138..147 zero. Processes 16 output cols per half.
//       (overlays dead SX after phase 2)
//   WDV at 15744 : 39 dup'd vertical weights (ull)
//   WDH at 15822 : 39 dup'd horizontal weights (ull)
#define OF_SY   0
#define OF_SX   6864
#define OF_SH   6864
#define SH_FSZ  2960
#define OF_WDV  15744
#define OF_WDH  15822
#define SMEM_A_FLOATS 15900

#define NEGINF (-3.402823466e38f)

template<bool EDGE>
__device__ __forceinline__ void load_grp(const float* p, int gc, bool r0, bool r1,
                                         float4& cs, float4& cm, float4& bv)
{
    const float4 a = *(const float4*)p;
    const float4 b = *(const float4*)(p + 56);
    const float4 c = *(const float4*)(p + 112);
    cs.x = a.x + b.x + c.x;  cs.y = a.y + b.y + c.y;
    cs.z = a.z + b.z + c.z;  cs.w = a.w + b.w + c.w;
    const float ax = r0 ? b.x : a.x, ay = r0 ? b.y : a.y,
                az = r0 ? b.z : a.z, aw = r0 ? b.w : a.w;
    const float cx = r1 ? b.x : c.x, cy = r1 ? b.y : c.y,
                cz = r1 ? b.z : c.z, cw = r1 ? b.w : c.w;
    cm.x = fmaxf(b.x, fmaxf(ax, cx));
    cm.y = fmaxf(b.y, fmaxf(ay, cy));
    cm.z = fmaxf(b.z, fmaxf(az, cz));
    cm.w = fmaxf(b.w, fmaxf(aw, cw));
    if (EDGE) {
        if ((unsigned)(gc + 0) >= 128u) cm.x = NEGINF;
        if ((unsigned)(gc + 1) >= 128u) cm.y = NEGINF;
        if ((unsigned)(gc + 2) >= 128u) cm.z = NEGINF;
        if ((unsigned)(gc + 3) >= 128u) cm.w = NEGINF;
    }
    bv = b;
}

template<int NOUT, bool EDGE>
__device__ __forceinline__ void compute_y_half(
    const float* sxb, float* syb, int gc0, bool r0, bool r1)
{
    float4 cs0, cm0, bv0;
    load_grp<EDGE>(sxb, gc0, r0, r1, cs0, cm0, bv0);
    #pragma unroll
    for (int g = 0; g < NOUT / 4; g++) {
        float4 cs1, cm1, bv1;
        load_grp<EDGE>(sxb + 4 * (g + 1), gc0 + 4 * (g + 1), r0, r1, cs1, cm1, bv1);
        const float s0 = cs0.x + cs0.y + cs0.z;
        const float s1 = cs0.y + cs0.z + cs0.w;
        const float s2 = cs0.z + cs0.w + cs1.x;
        const float s3 = cs0.w + cs1.x + cs1.y;
        const float m0 = fmaxf(cm0.x, fmaxf(cm0.y, cm0.z));
        const float m1 = fmaxf(cm0.y, fmaxf(cm0.z, cm0.w));
        const float m2 = fmaxf(cm0.z, fmaxf(cm0.w, cm1.x));
        const float m3 = fmaxf(cm0.w, fmaxf(cm1.x, cm1.y));
        float4 y;
        y.x = bv0.y + s0 * (1.f / 9.f) + m0;
        y.y = bv0.z + s1 * (1.f / 9.f) + m1;
        y.z = bv0.w + s2 * (1.f / 9.f) + m2;
        y.w = bv1.x + s3 * (1.f / 9.f) + m3;
        if (EDGE) {
            const int gy = gc0 + 1 + 4 * g;
            if ((unsigned)(gy + 0) >= 128u) y.x = 0.f;
            if ((unsigned)(gy + 1) >= 128u) y.y = 0.f;
            if ((unsigned)(gy + 2) >= 128u) y.z = 0.f;
            if ((unsigned)(gy + 3) >= 128u) y.w = 0.f;
        }
        *(float4*)(syb + 4 * g) = y;
        cs0 = cs1; cm0 = cm1; bv0 = bv1;
    }
}

__global__ __launch_bounds__(256, 3) void msca_dw_kernel(
    const float* __restrict__ x,
    const float* __restrict__ w55,    const float* __restrict__ b55,
    const float* __restrict__ w17_0,  const float* __restrict__ b17_0,
    const float* __restrict__ w17_1,  const float* __restrict__ b17_1,
    const float* __restrict__ w111_0, const float* __restrict__ b111_0,
    const float* __restrict__ w111_1, const float* __restrict__ b111_1,
    const float* __restrict__ w211_0, const float* __restrict__ b211_0,
    const float* __restrict__ w211_1, const float* __restrict__ b211_1)
{
    extern __shared__ float sm[];
    float* sy = sm + OF_SY;
    float* sx = sm + OF_SX;

    const int c0  = blockIdx.x * TW;
    const int c   = blockIdx.y;
    const int b   = blockIdx.z;
    const int tid = threadIdx.x;
    const bool interior = (c0 >= 11 && c0 + 42 <= 127);

    const float* xp = x + (size_t)(b * NC + c) * NPIX;

    // ---- phase 1: halo zeroing + dup'd weight tables + x tile load ----
    if (tid < 208) {           // sy rows 0,1,130,131
        const int h = tid / 52, j = tid - h * 52;
        sy[((h < 2) ? h : 128 + h) * 52 + j] = 0.f;
    }
    if (tid < 112) {           // sx rows 0, 129
        const int col = (tid < 56) ? tid : tid - 56;
        sx[((tid < 56) ? 0 : 129) * 56 + col] = 0.f;
    }
    sx[((tid >> 1) + 1) * 56 + 54 + (tid & 1)] = 0.f;   // sx cols 54,55 rows 1..128
    {   // dup'd weight tables: vertical (WDV) and horizontal (WDH)
        float2* wdv = (float2*)(sm + OF_WDV);
        float2* wdh = (float2*)(sm + OF_WDH);
        if (tid < 21)      { float w = w211_1[c * 21 + tid];        wdv[tid]      = make_float2(w, w); }
        else if (tid < 32) { float w = w111_1[c * 11 + (tid - 21)]; wdv[tid]      = make_float2(w, w); }
        else if (tid < 39) { float w = w17_1 [c * 7  + (tid - 32)]; wdv[tid]      = make_float2(w, w); }
        else if (tid < 60) { float w = w211_0[c * 21 + (tid - 39)]; wdh[tid - 39] = make_float2(w, w); }
        else if (tid < 71) { float w = w111_0[c * 11 + (tid - 60)]; wdh[tid - 39] = make_float2(w, w); }
        else if (tid < 78) { float w = w17_0 [c * 7  + (tid - 71)]; wdh[tid - 39] = make_float2(w, w); }
    }
    {   // x tile: sx[(ir+1)*56 + j] = x[ir][c0-11+j], division-free indexing
        int j  = tid % 54;
        int go = (tid / 54) * 128 + (c0 - 11) + j;
        int so = 56 + (tid / 54) * 56 + j;
        if (interior) {
            #pragma unroll
            for (int k = 0; k < 27; k++) {
                sx[so] = xp[go];
                so += 264; go += 552; j += 40;
                if (j >= 54) { j -= 54; so += 2; go += 74; }
            }
        } else {
            #pragma unroll
            for (int k = 0; k < 27; k++) {
                const int gc = c0 - 11 + j;
                sx[so] = ((unsigned)gc < NW) ? xp[go] : 0.f;
                so += 264; go += 552; j += 40;
                if (j >= 54) { j -= 54; so += 2; go += 74; }
            }
        }
    }
    __syncthreads();

    // ---- phase 2: y = x + avg3x3 + max3x3, direct per half-row ----
    {
        const int r = tid & 127;
        const bool r0 = (r == 0), r1 = (r == 127);
        const float* sxb = sx + r * 56;
        float* syb = sy + (r + 2) * 52;
        if (interior) {
            if (tid < 128) compute_y_half<28, false>(sxb,      syb,      c0 - 11, r0, r1);
            else           compute_y_half<24, false>(sxb + 28, syb + 28, c0 + 17, r0, r1);
        } else {
            if (tid < 128) compute_y_half<28, true >(sxb,      syb,      c0 - 11, r0, r1);
            else           compute_y_half<24, true >(sxb + 28, syb + 28, c0 + 17, r0, r1);
        }
    }
    __syncthreads();

    // ---- phases 3+4, two 16-column halves (SH fields hold 16 cols) ----
    float* sh21 = sm + OF_SH;
    float* sh11 = sh21 + SH_FSZ;
    float* sh7  = sh11 + SH_FSZ;
    const ull* wdh  = (const ull*)(sm + OF_WDH);
    const ull* wd21 = (const ull*)(sm + OF_WDV);
    const ull* wd11 = wd21 + 21;
    const ull* wd7  = wd21 + 32;

    const float bh21 = 3.f * b211_0[c];
    const float bh11 = 3.f * b111_0[c];
    const float bh7  = 3.f * b17_0[c];

    float* Tp = g_T + (size_t)(b * NC + c) * NPIX + c0;

    for (int half = 0; half < 2; half++) {
        const int ch0 = half << 4;

        if (half == 0) {
            // zero SH halo rows once (rows stay zero across halves)
            for (int idx = tid; idx < 960; idx += 256) {
                const int f = idx / 320, rest = idx - f * 320;
                const int hh = rest >> 4, col = rest & 15;
                (sm + OF_SH + f * SH_FSZ)[((hh < 10) ? hh : 128 + hh) * 20 + col] = 0.f;
            }
        }

        // ---- phase 3: horizontal convs for 16 cols (rolling pack) ----
        #pragma unroll
        for (int k = 0; k < 2; k++) {
            const int it = tid + (k << 8);          // 512 items: 128 rows x 4 groups
            const int r = it >> 2, oc4 = (it & 3) << 2;
            const float* yr = sy + (r + 2) * 52 + ch0 + oc4;
            float win[24];
            #pragma unroll
            for (int q = 0; q < 6; q++) {
                const float4 t4 = *(const float4*)(yr + 4 * q);
                win[4*q] = t4.x; win[4*q+1] = t4.y; win[4*q+2] = t4.z; win[4*q+3] = t4.w;
            }
            ull a21_0 = pack2(bh21, bh21), a21_2 = a21_0;
            ull a11_0 = pack2(bh11, bh11), a11_2 = a11_0;
            ull a7_0  = pack2(bh7,  bh7),  a7_2  = a7_0;
            #pragma unroll
            for (int i = 0; i < 23; i++) {
                const ull pk = pack2(win[i], win[i + 1]);
                if (i <= 20)           a21_0 = fma2(wdh[i],          pk, a21_0);
                if (i >= 2)            a21_2 = fma2(wdh[i - 2],      pk, a21_2);
                if (i >= 5 && i <= 15) a11_0 = fma2(wdh[21 + i - 5], pk, a11_0);
                if (i >= 7 && i <= 17) a11_2 = fma2(wdh[21 + i - 7], pk, a11_2);
                if (i >= 7 && i <= 13) a7_0  = fma2(wdh[32 + i - 7], pk, a7_0);
                if (i >= 9 && i <= 15) a7_2  = fma2(wdh[32 + i - 9], pk, a7_2);
            }
            const int so = (r + 10) * 20 + oc4;
            *(ulonglong2*)(sh21 + so) = make_ulonglong2(a21_0, a21_2);
            *(ulonglong2*)(sh11 + so) = make_ulonglong2(a11_0, a11_2);
            *(ulonglong2*)(sh7  + so) = make_ulonglong2(a7_0,  a7_2);
        }
        __syncthreads();

        // ---- phase 4: scalar 5x5 + packed vertical convs (1 item/thread) ----
        {
            float w5[25];
            #pragma unroll
            for (int i = 0; i < 25; i++) w5[i] = w55[c * 25 + i];
            const float tb = 3.f * (b55[c] + b17_1[c] + b111_1[c] + b211_1[c]);
            const ull tbp = pack2(tb, tb);

            const int oc2l = (tid & 7) * 2;
            const int r4   = (tid >> 3) * 4;
            const int oc2  = ch0 + oc2l;

            // scalar 5x5 on y
            float sacc[4][2] = {{0.f,0.f},{0.f,0.f},{0.f,0.f},{0.f,0.f}};
            #pragma unroll
            for (int rr = 0; rr < 8; rr++) {
                const float* yp = sy + (r4 + rr) * 52 + oc2 + 8;
                const float2 q0 = *(const float2*)yp;
                const float2 q1 = *(const float2*)(yp + 2);
                const float2 q2 = *(const float2*)(yp + 4);
                const float y0=q0.x, y1=q0.y, y2=q1.x, y3=q1.y, y4=q2.x, y5=q2.y;
                #pragma unroll
                for (int t = 0; t < 4; t++) {
                    const int kk = rr - t;
                    if (kk >= 0 && kk <= 4) {
                        const float* wr = w5 + kk * 5;
                        sacc[t][0] += wr[0]*y0 + wr[1]*y1 + wr[2]*y2 + wr[3]*y3 + wr[4]*y4;
                        sacc[t][1] += wr[0]*y1 + wr[1]*y2 + wr[2]*y3 + wr[3]*y4 + wr[4]*y5;
                    }
                }
            }

            ull acc[4] = {tbp, tbp, tbp, tbp};
            {   // v21: sh21 rows r4 .. r4+23
                const float* base = sh21 + r4 * 20 + oc2l;
                ull w0=0, w1=0, w2=0, w3=0;
                #pragma unroll
                for (int i = 0; i < 24; i++) {
                    w3 = w2; w2 = w1; w1 = w0;
                    if (i <= 20) w0 = wd21[i];
                    const ull v = *(const ull*)(base + i * 20);
                    if (i <= 20)           acc[0] = fma2(w0, v, acc[0]);
                    if (i >= 1 && i <= 21) acc[1] = fma2(w1, v, acc[1]);
                    if (i >= 2 && i <= 22) acc[2] = fma2(w2, v, acc[2]);
                    if (i >= 3)            acc[3] = fma2(w3, v, acc[3]);
                }
            }
            {   // v11: sh11 rows r4+5 .. r4+18
                const float* base = sh11 + (r4 + 5) * 20 + oc2l;
                ull w0=0, w1=0, w2=0, w3=0;
                #pragma unroll
                for (int i = 0; i < 14; i++) {
                    w3 = w2; w2 = w1; w1 = w0;
                    if (i <= 10) w0 = wd11[i];
                    const ull v = *(const ull*)(base + i * 20);
                    if (i <= 10)           acc[0] = fma2(w0, v, acc[0]);
                    if (i >= 1 && i <= 11) acc[1] = fma2(w1, v, acc[1]);
                    if (i >= 2 && i <= 12) acc[2] = fma2(w2, v, acc[2]);
                    if (i >= 3)            acc[3] = fma2(w3, v, acc[3]);
                }
            }
            {   // v7: sh7 rows r4+7 .. r4+16
                const float* base = sh7 + (r4 + 7) * 20 + oc2l;
                ull w0=0, w1=0, w2=0, w3=0;
                #pragma unroll
                for (int i = 0; i < 10; i++) {
                    w3 = w2; w2 = w1; w1 = w0;
                    if (i <= 6) w0 = wd7[i];
                    const ull v = *(const ull*)(base + i * 20);
                    if (i <= 6)           acc[0] = fma2(w0, v, acc[0]);
                    if (i >= 1 && i <= 7) acc[1] = fma2(w1, v, acc[1]);
                    if (i >= 2 && i <= 8) acc[2] = fma2(w2, v, acc[2]);
                    if (i >= 3)           acc[3] = fma2(w3, v, acc[3]);
                }
            }

            #pragma unroll
            for (int t = 0; t < 4; t++) {
                const float2 vr = unpack2(acc[t]);
                float2 o;
                o.x = vr.x + sacc[t][0];
                o.y = vr.y + sacc[t][1];
                *(float2*)&Tp[(r4 + t) * NW + oc2] = o;
            }
        }
        if (half == 0) __syncthreads();   // protect SH before next half's P3
    }
}

// ---------------------------------------------------------------------------
// Kernel B (R9 measured-best): out = (W[64x64] @ T + 3*b11) * x, packed f32x2.
// Block: 64 och x 256 pix, occ 2. Warp owns 8 och -> weight LDS.128 are
// warp-uniform broadcasts. Thread: 8 och x 8 pix (two 4-pixel quads).
// ---------------------------------------------------------------------------
#define PWPIX 256
#define SMEM_B_FLOATS (16384 + 4096 + 128)

__global__ __launch_bounds__(256, 2) void msca_pw_kernel(
    const float* __restrict__ x,
    const float* __restrict__ w11, const float* __restrict__ b11,
    float* __restrict__ out)
{
    extern __shared__ float sm[];
    float* sT = sm;                              // [64][256]
    float* sW = sm + 16384;                      // [64][64] raw
    float2* sBd = (float2*)(sm + 16384 + 4096);  // [64] dup'd 3*bias

    const int b   = blockIdx.y;
    const int p0  = blockIdx.x * PWPIX;
    const int tid = threadIdx.x;

    const float* Tb = g_T + (size_t)b * (NC * NPIX) + p0;
    #pragma unroll
    for (int k = 0; k < 16; k++) {
        const int idx = tid + (k << 8);              // 4096 float4s
        const int row = idx >> 6, c4 = idx & 63;
        ((float4*)sT)[idx] = *(const float4*)(Tb + (size_t)row * NPIX + (c4 << 2));
    }
    #pragma unroll
    for (int k = 0; k < 4; k++)
        ((float4*)sW)[tid + (k << 8)] = ((const float4*)w11)[tid + (k << 8)];
    if (tid < 64) { const float v = 3.f * b11[tid]; sBd[tid] = make_float2(v, v); }
    __syncthreads();

    const int lane = tid & 31;        // pixels lane*4..+3 and 128+lane*4..+3
    const int og8  = (tid >> 5) * 8;  // warp-uniform: och og8 .. og8+7

    ull acc[8][4];
    #pragma unroll
    for (int i = 0; i < 8; i++)
        #pragma unroll
        for (int p = 0; p < 4; p++) acc[i][p] = 0ull;

    #pragma unroll
    for (int k4 = 0; k4 < 64; k4 += 4) {
        float4 wq[8];
        #pragma unroll
        for (int i = 0; i < 8; i++)                 // warp-uniform LDS.128
            wq[i] = *(const float4*)&sW[(og8 + i) * 64 + k4];
        #pragma unroll
        for (int kk = 0; kk < 4; kk++) {
            const float* tr = sT + (k4 + kk) * 256 + (lane << 2);
            const ulonglong2 ta  = *(const ulonglong2*)tr;
            const ulonglong2 tb2 = *(const ulonglong2*)(tr + 128);
            #pragma unroll
            for (int i = 0; i < 8; i++) {
                const float f = (kk == 0) ? wq[i].x : (kk == 1) ? wq[i].y
                              : (kk == 2) ? wq[i].z : wq[i].w;
                const ull wd = pack2(f, f);
                acc[i][0] = fma2(wd, ta.x,  acc[i][0]);
                acc[i][1] = fma2(wd, ta.y,  acc[i][1]);
                acc[i][2] = fma2(wd, tb2.x, acc[i][2]);
                acc[i][3] = fma2(wd, tb2.y, acc[i][3]);
            }
        }
    }

    const float* xb = x + (size_t)b * (NC * NPIX) + p0;
    float*       ob = out + (size_t)b * (NC * NPIX) + p0;
    #pragma unroll
    for (int i = 0; i < 8; i++) {
        const int o = og8 + i;
        const ull bd = ((const ull*)sBd)[o];
        const size_t off0 = (size_t)o * NPIX + (lane << 2);
        const ulonglong2 xv0 = *(const ulonglong2*)(xb + off0);
        const ulonglong2 xv1 = *(const ulonglong2*)(xb + off0 + 128);
        ulonglong2 r0, r1;
        r0.x = mul2(add2(acc[i][0], bd), xv0.x);
        r0.y = mul2(add2(acc[i][1], bd), xv0.y);
        r1.x = mul2(add2(acc[i][2], bd), xv1.x);
        r1.y = mul2(add2(acc[i][3], bd), xv1.y);
        *(ulonglong2*)(ob + off0)       = r0;
        *(ulonglong2*)(ob + off0 + 128) = r1;
    }
}

// ---------------------------------------------------------------------------
extern "C" void kernel_launch(void* const* d_in, const int* in_sizes, int n_in,
                              void* d_out, int out_size)
{
    const float* x      = (const float*)d_in[0];
    const float* w55    = (const float*)d_in[1];
    const float* b55    = (const float*)d_in[2];
    const float* w17_0  = (const float*)d_in[3];
    const float* b17_0  = (const float*)d_in[4];
    const float* w17_1  = (const float*)d_in[5];
    const float* b17_1  = (const float*)d_in[6];
    const float* w111_0 = (const float*)d_in[7];
    const float* b111_0 = (const float*)d_in[8];
    const float* w111_1 = (const float*)d_in[9];
    const float* b111_1 = (const float*)d_in[10];
    const float* w211_0 = (const float*)d_in[11];
    const float* b211_0 = (const float*)d_in[12];
    const float* w211_1 = (const float*)d_in[13];
    const float* b211_1 = (const float*)d_in[14];
    const float* w11    = (const float*)d_in[15];
    const float* b11    = (const float*)d_in[16];
    float* out = (float*)d_out;

    const int smemA = SMEM_A_FLOATS * sizeof(float);   // 63,600 B (occ 3)
    const int smemB = SMEM_B_FLOATS * sizeof(float);   // 82,432 B

    cudaFuncSetAttribute(msca_dw_kernel, cudaFuncAttributeMaxDynamicSharedMemorySize, smemA);
    cudaFuncSetAttribute(msca_pw_kernel, cudaFuncAttributeMaxDynamicSharedMemorySize, smemB);

    dim3 gA(NW / TW, NC, NB);
    msca_dw_kernel<<<gA, 256, smemA>>>(x,
        w55, b55, w17_0, b17_0, w17_1, b17_1,
        w111_0, b111_0, w111_1, b111_1,
        w211_0, b211_0, w211_1, b211_1);

    dim3 gB(NPIX / PWPIX, NB);
    msca_pw_kernel<<<gB, 256, smemB>>>(x, w11, b11, out);
}

// round 11
// speedup vs baseline: 1.0777x; 1.0777x over previous
#include <cuda_runtime.h>

#define NB 16
#define NC 64
#define NH 128
#define NW 128
#define NPIX (NH*NW)
#define TW 32

typedef unsigned long long ull;

__device__ float g_T[(size_t)NB * NC * NH * NW];

// ---- packed fp32x2 helpers (exact IEEE fp32 per lane) ----
__device__ __forceinline__ ull fma2(ull a, ull b, ull c) {
    ull d;
    asm("fma.rn.f32x2 %0, %1, %2, %3;" : "=l"(d) : "l"(a), "l"(b), "l"(c));
    return d;
}
__device__ __forceinline__ ull add2(ull a, ull b) {
    ull d; asm("add.rn.f32x2 %0, %1, %2;" : "=l"(d) : "l"(a), "l"(b)); return d;
}
__device__ __forceinline__ ull mul2(ull a, ull b) {
    ull d; asm("mul.rn.f32x2 %0, %1, %2;" : "=l"(d) : "l"(a), "l"(b)); return d;
}
__device__ __forceinline__ ull pack2(float lo, float hi) {
    ull d; asm("mov.b64 %0, {%1, %2};" : "=l"(d) : "f"(lo), "f"(hi)); return d;
}
__device__ __forceinline__ float2 unpack2(ull v) {
    float2 f; asm("mov.b64 {%0, %1}, %2;" : "=f"(f.x), "=f"(f.y) : "l"(v)); return f;
}
__device__ __forceinline__ void cp_async16(unsigned s, const void* g) {
    asm volatile("cp.async.cg.shared.global [%0], [%1], 16;" :: "r"(s), "l"(g));
}

// smem layout (floats):
//   SY at 0     : [132][52] y (rows 0,1,130,131 zero; image row = i-2)
//   SX at 6864  : [130][56] x tile (rows 1..128; rows 0,129 and cols 54,55 zero)
//   SH21/SH11/SH7 at 6864 + f*4736 : [148][32], rows 0..9 & 138..147 zero
//   WDV at 21072 : 39 dup'd vertical weights (ull)
//   WDH at 21150 : 39 dup'd horizontal weights (ull)
#define OF_SY   0
#define OF_SX   6864
#define OF_SH   6864
#define SH_FSZ  4736
#define OF_WDV  21072
#define OF_WDH  21150
#define SMEM_A_FLOATS 21228

#define NEGINF (-3.402823466e38f)

template<bool EDGE>
__device__ __forceinline__ void load_grp(const float* p, int gc, bool r0, bool r1,
                                         float4& cs, float4& cm, float4& bv)
{
    const float4 a = *(const float4*)p;
    const float4 b = *(const float4*)(p + 56);
    const float4 c = *(const float4*)(p + 112);
    cs.x = a.x + b.x + c.x;  cs.y = a.y + b.y + c.y;
    cs.z = a.z + b.z + c.z;  cs.w = a.w + b.w + c.w;
    const float ax = r0 ? b.x : a.x, ay = r0 ? b.y : a.y,
                az = r0 ? b.z : a.z, aw = r0 ? b.w : a.w;
    const float cx = r1 ? b.x : c.x, cy = r1 ? b.y : c.y,
                cz = r1 ? b.z : c.z, cw = r1 ? b.w : c.w;
    cm.x = fmaxf(b.x, fmaxf(ax, cx));
    cm.y = fmaxf(b.y, fmaxf(ay, cy));
    cm.z = fmaxf(b.z, fmaxf(az, cz));
    cm.w = fmaxf(b.w, fmaxf(aw, cw));
    if (EDGE) {
        if ((unsigned)(gc + 0) >= 128u) cm.x = NEGINF;
        if ((unsigned)(gc + 1) >= 128u) cm.y = NEGINF;
        if ((unsigned)(gc + 2) >= 128u) cm.z = NEGINF;
        if ((unsigned)(gc + 3) >= 128u) cm.w = NEGINF;
    }
    bv = b;
}

template<int NOUT, bool EDGE>
__device__ __forceinline__ void compute_y_half(
    const float* sxb, float* syb, int gc0, bool r0, bool r1)
{
    float4 cs0, cm0, bv0;
    load_grp<EDGE>(sxb, gc0, r0, r1, cs0, cm0, bv0);
    #pragma unroll
    for (int g = 0; g < NOUT / 4; g++) {
        float4 cs1, cm1, bv1;
        load_grp<EDGE>(sxb + 4 * (g + 1), gc0 + 4 * (g + 1), r0, r1, cs1, cm1, bv1);
        const float s0 = cs0.x + cs0.y + cs0.z;
        const float s1 = cs0.y + cs0.z + cs0.w;
        const float s2 = cs0.z + cs0.w + cs1.x;
        const float s3 = cs0.w + cs1.x + cs1.y;
        const float m0 = fmaxf(cm0.x, fmaxf(cm0.y, cm0.z));
        const float m1 = fmaxf(cm0.y, fmaxf(cm0.z, cm0.w));
        const float m2 = fmaxf(cm0.z, fmaxf(cm0.w, cm1.x));
        const float m3 = fmaxf(cm0.w, fmaxf(cm1.x, cm1.y));
        float4 y;
        y.x = bv0.y + s0 * (1.f / 9.f) + m0;
        y.y = bv0.z + s1 * (1.f / 9.f) + m1;
        y.z = bv0.w + s2 * (1.f / 9.f) + m2;
        y.w = bv1.x + s3 * (1.f / 9.f) + m3;
        if (EDGE) {
            const int gy = gc0 + 1 + 4 * g;
            if ((unsigned)(gy + 0) >= 128u) y.x = 0.f;
            if ((unsigned)(gy + 1) >= 128u) y.y = 0.f;
            if ((unsigned)(gy + 2) >= 128u) y.z = 0.f;
            if ((unsigned)(gy + 3) >= 128u) y.w = 0.f;
        }
        *(float4*)(syb + 4 * g) = y;
        cs0 = cs1; cm0 = cm1; bv0 = bv1;
    }
}

__global__ __launch_bounds__(256, 2) void msca_dw_kernel(
    const float* __restrict__ x,
    const float* __restrict__ w55,    const float* __restrict__ b55,
    const float* __restrict__ w17_0,  const float* __restrict__ b17_0,
    const float* __restrict__ w17_1,  const float* __restrict__ b17_1,
    const float* __restrict__ w111_0, const float* __restrict__ b111_0,
    const float* __restrict__ w111_1, const float* __restrict__ b111_1,
    const float* __restrict__ w211_0, const float* __restrict__ b211_0,
    const float* __restrict__ w211_1, const float* __restrict__ b211_1)
{
    extern __shared__ float sm[];
    float* sy = sm + OF_SY;
    float* sx = sm + OF_SX;

    const int c0  = blockIdx.x * TW;
    const int c   = blockIdx.y;
    const int b   = blockIdx.z;
    const int tid = threadIdx.x;
    const bool interior = (c0 >= 11 && c0 + 42 <= 127);

    const float* xp = x + (size_t)(b * NC + c) * NPIX;

    // ---- phase 1: halo zeroing + dup'd weight tables + x tile load ----
    if (tid < 208) {           // sy rows 0,1,130,131
        const int h = tid / 52, j = tid - h * 52;
        sy[((h < 2) ? h : 128 + h) * 52 + j] = 0.f;
    }
    if (tid < 112) {           // sx rows 0, 129
        const int col = (tid < 56) ? tid : tid - 56;
        sx[((tid < 56) ? 0 : 129) * 56 + col] = 0.f;
    }
    sx[((tid >> 1) + 1) * 56 + 54 + (tid & 1)] = 0.f;   // sx cols 54,55 rows 1..128
    {   // dup'd weight tables: vertical (WDV) and horizontal (WDH)
        float2* wdv = (float2*)(sm + OF_WDV);
        float2* wdh = (float2*)(sm + OF_WDH);
        if (tid < 21)      { float w = w211_1[c * 21 + tid];        wdv[tid]      = make_float2(w, w); }
        else if (tid < 32) { float w = w111_1[c * 11 + (tid - 21)]; wdv[tid]      = make_float2(w, w); }
        else if (tid < 39) { float w = w17_1 [c * 7  + (tid - 32)]; wdv[tid]      = make_float2(w, w); }
        else if (tid < 60) { float w = w211_0[c * 21 + (tid - 39)]; wdh[tid - 39] = make_float2(w, w); }
        else if (tid < 71) { float w = w111_0[c * 11 + (tid - 60)]; wdh[tid - 39] = make_float2(w, w); }
        else if (tid < 78) { float w = w17_0 [c * 7  + (tid - 71)]; wdh[tid - 39] = make_float2(w, w); }
    }
    {   // x tile: sx[(ir+1)*56 + j] = x[ir][c0-11+j], division-free indexing
        int j  = tid % 54;
        int go = (tid / 54) * 128 + (c0 - 11) + j;
        int so = 56 + (tid / 54) * 56 + j;
        if (interior) {
            #pragma unroll
            for (int k = 0; k < 27; k++) {
                sx[so] = xp[go];
                so += 264; go += 552; j += 40;
                if (j >= 54) { j -= 54; so += 2; go += 74; }
            }
        } else {
            #pragma unroll
            for (int k = 0; k < 27; k++) {
                const int gc = c0 - 11 + j;
                sx[so] = ((unsigned)gc < NW) ? xp[go] : 0.f;
                so += 264; go += 552; j += 40;
                if (j >= 54) { j -= 54; so += 2; go += 74; }
            }
        }
    }
    __syncthreads();

    // ---- phase 2: y = x + avg3x3 + max3x3, direct per half-row ----
    {
        const int r = tid & 127;
        const bool r0 = (r == 0), r1 = (r == 127);
        const float* sxb = sx + r * 56;
        float* syb = sy + (r + 2) * 52;
        if (interior) {
            if (tid < 128) compute_y_half<28, false>(sxb,      syb,      c0 - 11, r0, r1);
            else           compute_y_half<24, false>(sxb + 28, syb + 28, c0 + 17, r0, r1);
        } else {
            if (tid < 128) compute_y_half<28, true >(sxb,      syb,      c0 - 11, r0, r1);
            else           compute_y_half<24, true >(sxb + 28, syb + 28, c0 + 17, r0, r1);
        }
    }
    __syncthreads();

    // ---- phase 3: horizontal convs, packed over column pairs ----
    float* sh21 = sm + OF_SH;
    float* sh11 = sh21 + SH_FSZ;
    float* sh7  = sh11 + SH_FSZ;

    for (int idx = tid; idx < 1920; idx += 256) {          // zero sh halo rows
        const int f = idx / 640, rest = idx - f * 640;
        const int h = rest >> 5, col = rest & 31;
        (sm + OF_SH + f * SH_FSZ)[((h < 10) ? h : 128 + h) * 32 + col] = 0.f;
    }

    {
        const ull* wdh = (const ull*)(sm + OF_WDH);
        const float bh21 = 3.f * b211_0[c];
        const float bh11 = 3.f * b111_0[c];
        const float bh7  = 3.f * b17_0[c];
        const ull b21p = pack2(bh21, bh21), b11p = pack2(bh11, bh11), b7p = pack2(bh7, bh7);

        #pragma unroll
        for (int k = 0; k < 4; k++) {
            const int it = tid + (k << 8);
            const int r = it >> 3, oc4 = (it & 7) << 2;
            const float* yr = sy + (r + 2) * 52 + oc4;
            float win[24];
            #pragma unroll
            for (int q = 0; q < 6; q++) {
                const float4 t4 = *(const float4*)(yr + 4 * q);
                win[4*q] = t4.x; win[4*q+1] = t4.y; win[4*q+2] = t4.z; win[4*q+3] = t4.w;
            }
            ull pw[23];
            #pragma unroll
            for (int j = 0; j < 23; j++) pw[j] = pack2(win[j], win[j + 1]);

            ull a21_0 = b21p, a21_2 = b21p;
            ull a11_0 = b11p, a11_2 = b11p;
            ull a7_0  = b7p,  a7_2  = b7p;
            #pragma unroll
            for (int i = 0; i < 21; i++) {
                const ull w = wdh[i];
                a21_0 = fma2(w, pw[i],     a21_0);
                a21_2 = fma2(w, pw[i + 2], a21_2);
            }
            #pragma unroll
            for (int i = 0; i < 11; i++) {
                const ull w = wdh[21 + i];
                a11_0 = fma2(w, pw[5 + i], a11_0);
                a11_2 = fma2(w, pw[7 + i], a11_2);
            }
            #pragma unroll
            for (int i = 0; i < 7; i++) {
                const ull w = wdh[32 + i];
                a7_0 = fma2(w, pw[7 + i], a7_0);
                a7_2 = fma2(w, pw[9 + i], a7_2);
            }
            const int so = (r + 10) * 32 + oc4;
            *(ulonglong2*)(sh21 + so) = make_ulonglong2(a21_0, a21_2);
            *(ulonglong2*)(sh11 + so) = make_ulonglong2(a11_0, a11_2);
            *(ulonglong2*)(sh7  + so) = make_ulonglong2(a7_0,  a7_2);
        }
    }
    __syncthreads();

    // ---- phase 4: packed 5x5 + packed vertical convs (4 rows x 2 cols/item) ----
    ull w5d[25];
    #pragma unroll
    for (int i = 0; i < 25; i++) { const float w = w55[c * 25 + i]; w5d[i] = pack2(w, w); }
    const float tb = 3.f * (b55[c] + b17_1[c] + b111_1[c] + b211_1[c]);
    const ull tbp = pack2(tb, tb);

    const ull* wd21 = (const ull*)(sm + OF_WDV);
    const ull* wd11 = wd21 + 21;
    const ull* wd7  = wd21 + 32;

    float* Tp = g_T + (size_t)(b * NC + c) * NPIX + c0;

    #pragma unroll
    for (int k = 0; k < 2; k++) {
        const int it = tid + (k << 8);            // 512 items
        const int oc2 = (it & 15) * 2;
        const int r4  = (it >> 4) * 4;

        ull acc[4] = {tbp, tbp, tbp, tbp};

        // packed 5x5 on y: data pairs from aligned ull loads + 2 packs/row
        #pragma unroll
        for (int rr = 0; rr < 8; rr++) {
            const float* yp = sy + (r4 + rr) * 52 + oc2 + 8;
            const ull p0 = *(const ull*)yp;
            const ull p2 = *(const ull*)(yp + 2);
            const ull p4 = *(const ull*)(yp + 4);
            const float2 f0 = unpack2(p0);
            const float2 f2 = unpack2(p2);
            const float2 f4 = unpack2(p4);
            const ull p1 = pack2(f0.y, f2.x);
            const ull p3 = pack2(f2.y, f4.x);
            #pragma unroll
            for (int t = 0; t < 4; t++) {
                const int kk = rr - t;
                if (kk >= 0 && kk <= 4) {
                    const ull* wr = w5d + kk * 5;
                    acc[t] = fma2(wr[0], p0, acc[t]);
                    acc[t] = fma2(wr[1], p1, acc[t]);
                    acc[t] = fma2(wr[2], p2, acc[t]);
                    acc[t] = fma2(wr[3], p3, acc[t]);
                    acc[t] = fma2(wr[4], p4, acc[t]);
                }
            }
        }
        {   // v21: sh21 rows r4 .. r4+23
            const float* base = sh21 + r4 * 32 + oc2;
            ull w0=0, w1=0, w2=0, w3=0;
            #pragma unroll
            for (int i = 0; i < 24; i++) {
                w3 = w2; w2 = w1; w1 = w0;
                if (i <= 20) w0 = wd21[i];
                const ull v = *(const ull*)(base + i * 32);
                if (i <= 20)           acc[0] = fma2(w0, v, acc[0]);
                if (i >= 1 && i <= 21) acc[1] = fma2(w1, v, acc[1]);
                if (i >= 2 && i <= 22) acc[2] = fma2(w2, v, acc[2]);
                if (i >= 3)            acc[3] = fma2(w3, v, acc[3]);
            }
        }
        {   // v11: sh11 rows r4+5 .. r4+18
            const float* base = sh11 + (r4 + 5) * 32 + oc2;
            ull w0=0, w1=0, w2=0, w3=0;
            #pragma unroll
            for (int i = 0; i < 14; i++) {
                w3 = w2; w2 = w1; w1 = w0;
                if (i <= 10) w0 = wd11[i];
                const ull v = *(const ull*)(base + i * 32);
                if (i <= 10)           acc[0] = fma2(w0, v, acc[0]);
                if (i >= 1 && i <= 11) acc[1] = fma2(w1, v, acc[1]);
                if (i >= 2 && i <= 12) acc[2] = fma2(w2, v, acc[2]);
                if (i >= 3)            acc[3] = fma2(w3, v, acc[3]);
            }
        }
        {   // v7: sh7 rows r4+7 .. r4+16
            const float* base = sh7 + (r4 + 7) * 32 + oc2;
            ull w0=0, w1=0, w2=0, w3=0;
            #pragma unroll
            for (int i = 0; i < 10; i++) {
                w3 = w2; w2 = w1; w1 = w0;
                if (i <= 6) w0 = wd7[i];
                const ull v = *(const ull*)(base + i * 32);
                if (i <= 6)           acc[0] = fma2(w0, v, acc[0]);
                if (i >= 1 && i <= 7) acc[1] = fma2(w1, v, acc[1]);
                if (i >= 2 && i <= 8) acc[2] = fma2(w2, v, acc[2]);
                if (i >= 3)           acc[3] = fma2(w3, v, acc[3]);
            }
        }

        #pragma unroll
        for (int t = 0; t < 4; t++) {
            const float2 vr = unpack2(acc[t]);
            *(float2*)&Tp[(r4 + t) * NW + oc2] = vr;
        }
    }
}

// ---------------------------------------------------------------------------
// Kernel B: out = (W[64x64] @ T + 3*b11) * x, packed f32x2, cp.async
// double-buffered: T rows 0-31 + W in group 0, T rows 32-63 in group 1;
// compute k<32 overlaps the group-1 stream. Warp-uniform weight rows.
// ---------------------------------------------------------------------------
#define PWPIX 256
#define SMEM_B_FLOATS (16384 + 4096 + 128)

__device__ __forceinline__ void pw_compute_half(
    const float* sT, const float* sW, int lane, int og8, ull acc[8][4], int kbeg)
{
    #pragma unroll
    for (int k4 = 0; k4 < 32; k4 += 4) {
        float4 wq[8];
        #pragma unroll
        for (int i = 0; i < 8; i++)                 // warp-uniform LDS.128
            wq[i] = *(const float4*)&sW[(og8 + i) * 64 + kbeg + k4];
        #pragma unroll
        for (int kk = 0; kk < 4; kk++) {
            const float* tr = sT + (kbeg + k4 + kk) * 256 + (lane << 2);
            const ulonglong2 ta  = *(const ulonglong2*)tr;
            const ulonglong2 tb2 = *(const ulonglong2*)(tr + 128);
            #pragma unroll
            for (int i = 0; i < 8; i++) {
                const float f = (kk == 0) ? wq[i].x : (kk == 1) ? wq[i].y
                              : (kk == 2) ? wq[i].z : wq[i].w;
                const ull wd = pack2(f, f);
                acc[i][0] = fma2(wd, ta.x,  acc[i][0]);
                acc[i][1] = fma2(wd, ta.y,  acc[i][1]);
                acc[i][2] = fma2(wd, tb2.x, acc[i][2]);
                acc[i][3] = fma2(wd, tb2.y, acc[i][3]);
            }
        }
    }
}

__global__ __launch_bounds__(256, 2) void msca_pw_kernel(
    const float* __restrict__ x,
    const float* __restrict__ w11, const float* __restrict__ b11,
    float* __restrict__ out)
{
    extern __shared__ float sm[];
    float* sT = sm;                              // [64][256]
    float* sW = sm + 16384;                      // [64][64] raw
    float2* sBd = (float2*)(sm + 16384 + 4096);  // [64] dup'd 3*bias

    const int b   = blockIdx.y;
    const int p0  = blockIdx.x * PWPIX;
    const int tid = threadIdx.x;

    const float* Tb = g_T + (size_t)b * (NC * NPIX) + p0;
    const unsigned sTa = (unsigned)__cvta_generic_to_shared(sT);
    const unsigned sWa = (unsigned)__cvta_generic_to_shared(sW);

    // group 0: T rows 0..31 + all weights
    #pragma unroll
    for (int k = 0; k < 8; k++) {
        const int idx = tid + (k << 8);              // rows 0..31
        const int row = idx >> 6, c4 = idx & 63;
        cp_async16(sTa + idx * 16, Tb + (size_t)row * NPIX + (c4 << 2));
    }
    #pragma unroll
    for (int k = 0; k < 4; k++) {
        const int idx = tid + (k << 8);
        cp_async16(sWa + idx * 16, w11 + idx * 4);
    }
    asm volatile("cp.async.commit_group;" ::: "memory");

    // group 1: T rows 32..63
    #pragma unroll
    for (int k = 8; k < 16; k++) {
        const int idx = tid + (k << 8);
        const int row = idx >> 6, c4 = idx & 63;
        cp_async16(sTa + idx * 16, Tb + (size_t)row * NPIX + (c4 << 2));
    }
    asm volatile("cp.async.commit_group;" ::: "memory");

    if (tid < 64) { const float v = 3.f * b11[tid]; sBd[tid] = make_float2(v, v); }

    asm volatile("cp.async.wait_group 1;" ::: "memory");
    __syncthreads();

    const int lane = tid & 31;        // pixels lane*4..+3 and 128+lane*4..+3
    const int og8  = (tid >> 5) * 8;  // warp-uniform: och og8 .. og8+7

    ull acc[8][4];
    #pragma unroll
    for (int i = 0; i < 8; i++)
        #pragma unroll
        for (int p = 0; p < 4; p++) acc[i][p] = 0ull;

    pw_compute_half(sT, sW, lane, og8, acc, 0);     // k 0..31 (group 1 streaming)

    asm volatile("cp.async.wait_group 0;" ::: "memory");
    __syncthreads();

    pw_compute_half(sT, sW, lane, og8, acc, 32);    // k 32..63

    const float* xb = x + (size_t)b * (NC * NPIX) + p0;
    float*       ob = out + (size_t)b * (NC * NPIX) + p0;
    #pragma unroll
    for (int i = 0; i < 8; i++) {
        const int o = og8 + i;
        const ull bd = ((const ull*)sBd)[o];
        const size_t off0 = (size_t)o * NPIX + (lane << 2);
        const ulonglong2 xv0 = *(const ulonglong2*)(xb + off0);
        const ulonglong2 xv1 = *(const ulonglong2*)(xb + off0 + 128);
        ulonglong2 r0, r1;
        r0.x = mul2(add2(acc[i][0], bd), xv0.x);
        r0.y = mul2(add2(acc[i][1], bd), xv0.y);
        r1.x = mul2(add2(acc[i][2], bd), xv1.x);
        r1.y = mul2(add2(acc[i][3], bd), xv1.y);
        *(ulonglong2*)(ob + off0)       = r0;
        *(ulonglong2*)(ob + off0 + 128) = r1;
    }
}

// ---------------------------------------------------------------------------
extern "C" void kernel_launch(void* const* d_in, const int* in_sizes, int n_in,
                              void* d_out, int out_size)
{
    const float* x      = (const float*)d_in[0];
    const float* w55    = (const float*)d_in[1];
    const float* b55    = (const float*)d_in[2];
    const float* w17_0  = (const float*)d_in[3];
    const float* b17_0  = (const float*)d_in[4];
    const float* w17_1  = (const float*)d_in[5];
    const float* b17_1  = (const float*)d_in[6];
    const float* w111_0 = (const float*)d_in[7];
    const float* b111_0 = (const float*)d_in[8];
    const float* w111_1 = (const float*)d_in[9];
    const float* b111_1 = (const float*)d_in[10];
    const float* w211_0 = (const float*)d_in[11];
    const float* b211_0 = (const float*)d_in[12];
    const float* w211_1 = (const float*)d_in[13];
    const float* b211_1 = (const float*)d_in[14];
    const float* w11    = (const float*)d_in[15];
    const float* b11    = (const float*)d_in[16];
    float* out = (float*)d_out;

    const int smemA = SMEM_A_FLOATS * sizeof(float);   // 84,912 B
    const int smemB = SMEM_B_FLOATS * sizeof(float);   // 82,432 B

    cudaFuncSetAttribute(msca_dw_kernel, cudaFuncAttributeMaxDynamicSharedMemorySize, smemA);
    cudaFuncSetAttribute(msca_pw_kernel, cudaFuncAttributeMaxDynamicSharedMemorySize, smemB);

    dim3 gA(NW / TW, NC, NB);
    msca_dw_kernel<<<gA, 256, smemA>>>(x,
        w55, b55, w17_0, b17_0, w17_1, b17_1,
        w111_0, b111_0, w111_1, b111_1,
        w211_0, b211_0, w211_1, b211_1);

    dim3 gB(NPIX / PWPIX, NB);
    msca_pw_kernel<<<gB, 256, smemB>>>(x, w11, b11, out);
}